// round 6
// baseline (speedup 1.0000x reference)
#include <cuda_runtime.h>
#include <math.h>

#define T_STEPS 1000
#define BATCH   16
#define MEL     80
#define HID     512
#define NCLS    64
#define NROWS   (T_STEPS*BATCH)      // 16000

#define SCAN_CTAS   64
#define COLS_PER_CTA (HID/SCAN_CTAS) // 8

// ---------------- scratch (device globals; no allocation allowed) ----------
__device__ float    g_xn0[NROWS*MEL];
__device__ float    g_be0[NROWS*HID];
__device__ float    g_xn1[NROWS*HID];
__device__ float    g_be1[NROWS*HID];
__device__ float    g_hall[NROWS*HID];
__device__ float    g_scale1[NROWS];
__device__ float    g_err[BATCH*HID];
__device__ float    g_normp[BATCH*128];   // [b][cta*2 + half] partial norms
__device__ float    g_hzero[BATCH*HID];
__device__ unsigned g_ctr[2*T_STEPS];

// ---------------- zero scratch each graph replay ---------------------------
__global__ void zero_scratch() {
    int i = blockIdx.x*blockDim.x + threadIdx.x;
    if (i < 2*T_STEPS)  g_ctr[i]   = 0u;
    if (i < BATCH*HID)  g_hzero[i] = 0.f;
}

// ---------------- x_norm for cell0 input (feats) ---------------------------
__global__ void xnorm0_kernel(const float* __restrict__ feats) {
    int w    = (blockIdx.x*blockDim.x + threadIdx.x) >> 5;
    int lane = threadIdx.x & 31;
    if (w >= NROWS) return;
    int t = w >> 4, b = w & 15;
    const float* row = feats + ((size_t)b*T_STEPS + t)*MEL;
    float v0 = row[lane];
    float v1 = row[lane+32];
    float v2 = (lane < MEL-64) ? row[lane+64] : 0.f;
    float s = v0*v0 + v1*v1 + v2*v2;
    #pragma unroll
    for (int off = 16; off; off >>= 1) s += __shfl_xor_sync(0xffffffffu, s, off);
    float sc  = fmaxf(sqrtf(s), 1e-6f);
    float inv = 1.f/sc;
    float* o = g_xn0 + (size_t)w*MEL;
    o[lane]    = fminf(fmaxf(v0*inv, -1.f), 1.f);
    o[lane+32] = fminf(fmaxf(v1*inv, -1.f), 1.f);
    if (lane < MEL-64) o[lane+64] = fminf(fmaxf(v2*inv, -1.f), 1.f);
}

// ---------------- x_norm + scale for cell1 input (be0) ---------------------
__global__ void xnorm1_kernel() {
    int w    = (blockIdx.x*blockDim.x + threadIdx.x) >> 5;
    int lane = threadIdx.x & 31;
    if (w >= NROWS) return;
    const float4* row = (const float4*)(g_be0 + (size_t)w*HID);
    float4 v[4];
    float s = 0.f;
    #pragma unroll
    for (int i = 0; i < 4; i++) {
        v[i] = row[lane + 32*i];
        s += v[i].x*v[i].x + v[i].y*v[i].y + v[i].z*v[i].z + v[i].w*v[i].w;
    }
    #pragma unroll
    for (int off = 16; off; off >>= 1) s += __shfl_xor_sync(0xffffffffu, s, off);
    float sc = fmaxf(sqrtf(s), 1e-6f);
    if (lane == 0) g_scale1[w] = sc;
    float inv = 1.f/sc;
    float4* o = (float4*)(g_xn1 + (size_t)w*HID);
    #pragma unroll
    for (int i = 0; i < 4; i++) {
        float4 u = v[i];
        u.x = fminf(fmaxf(u.x*inv,-1.f),1.f);
        u.y = fminf(fmaxf(u.y*inv,-1.f),1.f);
        u.z = fminf(fmaxf(u.z*inv,-1.f),1.f);
        u.w = fminf(fmaxf(u.w*inv,-1.f),1.f);
        o[lane + 32*i] = u;
    }
}

// ---------------- generic tiled SGEMM: C = A(M,K) @ W(N,K)^T ---------------
__global__ __launch_bounds__(256) void sgemm_nt(
    const float* __restrict__ A, int lda,
    const float* __restrict__ W, int ldw,
    float*       __restrict__ C, int ldc,
    int K, int accumulate, const float* __restrict__ bias, int remap)
{
    __shared__ float As[16][64];
    __shared__ float Ws[16][64];
    int bm = blockIdx.y*64, bn = blockIdx.x*64;
    int tid = threadIdx.x;
    int lr  = tid >> 2;
    int kq  = (tid & 3)*4;
    int tx  = tid & 15, ty = tid >> 4;
    float acc[4][4];
    #pragma unroll
    for (int i=0;i<4;i++)
        #pragma unroll
        for (int j=0;j<4;j++) acc[i][j]=0.f;

    for (int k0 = 0; k0 < K; k0 += 16) {
        float4 av = *(const float4*)(A + (size_t)(bm+lr)*lda + k0 + kq);
        float4 wv = *(const float4*)(W + (size_t)(bn+lr)*ldw + k0 + kq);
        As[kq+0][lr]=av.x; As[kq+1][lr]=av.y; As[kq+2][lr]=av.z; As[kq+3][lr]=av.w;
        Ws[kq+0][lr]=wv.x; Ws[kq+1][lr]=wv.y; Ws[kq+2][lr]=wv.z; Ws[kq+3][lr]=wv.w;
        __syncthreads();
        #pragma unroll
        for (int k = 0; k < 16; k++) {
            float4 a4 = *(float4*)&As[k][ty*4];
            float4 w4 = *(float4*)&Ws[k][tx*4];
            float ar[4] = {a4.x, a4.y, a4.z, a4.w};
            float wr[4] = {w4.x, w4.y, w4.z, w4.w};
            #pragma unroll
            for (int i=0;i<4;i++)
                #pragma unroll
                for (int j=0;j<4;j++) acc[i][j] += ar[i]*wr[j];
        }
        __syncthreads();
    }
    #pragma unroll
    for (int i = 0; i < 4; i++) {
        int r = bm + ty*4 + i;
        int orow = remap ? ((r & 15)*T_STEPS + (r >> 4)) : r;
        #pragma unroll
        for (int j = 0; j < 4; j++) {
            int cidx = bn + tx*4 + j;
            float val = acc[i][j];
            if (bias) val += bias[cidx];
            float* p = C + (size_t)orow*ldc + cidx;
            if (accumulate) val += *p;
            *p = val;
        }
    }
}

// ---------------- fence-free grid barrier (release/acquire) -----------------
__device__ __forceinline__ void gbar(unsigned* c) {
    __syncthreads();
    if (threadIdx.x == 0) {
        asm volatile("red.release.gpu.global.add.u32 [%0], 1;" :: "l"(c) : "memory");
        unsigned v;
        do {
            asm volatile("ld.acquire.gpu.global.u32 %0, [%1];" : "=r"(v) : "l"(c) : "memory");
        } while (v < SCAN_CTAS);
    }
    __syncthreads();
}

// ---------------- f32x2 helpers ---------------------------------------------
__device__ __forceinline__ void fma2(unsigned long long& d,
                                     unsigned long long a, unsigned long long b) {
    asm volatile("fma.rn.f32x2 %0, %1, %2, %0;" : "+l"(d) : "l"(a), "l"(b));
}
__device__ __forceinline__ float hadd2(unsigned long long v) {
    unsigned lo, hi;
    asm("mov.b64 {%0, %1}, %2;" : "=r"(lo), "=r"(hi) : "l"(v));
    return __uint_as_float(lo) + __uint_as_float(hi);
}

// ---------------- weight preload: 32 ull per matrix per thread --------------
// layout: w[i*8 + c*2 + q], i = k-iter (kf=(lane+32i)*4), c = col 0..3, q = k-half
__device__ __forceinline__ void load_wreg(const float* __restrict__ Wm,
                                          int mbase, int c0, int lane,
                                          unsigned long long w[32]) {
    #pragma unroll
    for (int i = 0; i < 4; i++) {
        int kf = (lane + 32*i)*4;
        #pragma unroll
        for (int c = 0; c < 4; c++) {
            ulonglong2 wp = *(const ulonglong2*)(Wm + (size_t)(mbase + c0 + c)*HID + kf);
            w[i*8 + c*2 + 0] = wp.x;   // (w[k], w[k+1])
            w[i*8 + c*2 + 1] = wp.y;   // (w[k+2], w[k+3])
        }
    }
}

// ---------------- inner GEMM: reg weights, f32x2 k-pair accumulation --------
// outputs out[16] = full (4 rows x 4 cols) dot products, identical on all lanes
__device__ __forceinline__ void tile_mm_reg(const unsigned long long* __restrict__ w,
                                            const float* __restrict__ src,
                                            int r0, int lane, float out[16])
{
    unsigned long long acc[16];
    #pragma unroll
    for (int j = 0; j < 16; j++) acc[j] = 0ull;
    #pragma unroll
    for (int i = 0; i < 4; i++) {
        int kf = (lane + 32*i)*4;
        #pragma unroll
        for (int r = 0; r < 4; r++) {
            ulonglong2 hv = *(const ulonglong2*)&src[(r0+r)*HID + kf];
            #pragma unroll
            for (int c = 0; c < 4; c++) {
                fma2(acc[r*4+c], hv.x, w[i*8 + c*2 + 0]);
                fma2(acc[r*4+c], hv.y, w[i*8 + c*2 + 1]);
            }
        }
    }
    #pragma unroll
    for (int j = 0; j < 16; j++) out[j] = hadd2(acc[j]);
    #pragma unroll
    for (int off = 16; off; off >>= 1) {
        #pragma unroll
        for (int j = 0; j < 16; j++)
            out[j] += __shfl_xor_sync(0xffffffffu, out[j], off);
    }
}

__device__ __forceinline__ float pick16(const float acc[16], int lane) {
    float v = acc[0];
    #pragma unroll
    for (int j = 1; j < 16; j++) if (lane == j) v = acc[j];
    return v;
}

// ---------------- persistent sequential scan over T ------------------------
__global__ __launch_bounds__(256, 1) void scan_kernel(
    const float* __restrict__ C1, const float* __restrict__ W1,
    const float* __restrict__ a1, const float* __restrict__ taup,
    const float* __restrict__ gamp)
{
    extern __shared__ float sm[];
    float* hb   = sm;                          // 16*512 (h_{t-1})
    float* eb   = hb + BATCH*HID;              // 16*512 (error)
    float* sga  = eb + BATCH*HID;              // 8
    float* snorm= sga + COLS_PER_CTA;          // 16

    const int g = blockIdx.x, tid = threadIdx.x;
    const int mbase = g*COLS_PER_CTA;

    if (tid < COLS_PER_CTA) sga[tid] = 1.f/(1.f + expf(-a1[mbase+tid]));
    const float tau = taup[0], gam = gamp[0];

    const int warp = tid >> 5, lane = tid & 31;
    const int r0 = (warp & 3)*4;      // batch-row group
    const int c0 = (warp >> 2)*4;     // col group within CTA slice
    const int rr = lane >> 2, cc = lane & 3;
    const int bql = r0 + rr;                  // this lane's batch row (lane<16)
    const int mql = mbase + c0 + cc;          // this lane's output column

    // step-invariant weights in registers (32+32 ull = 128 regs)
    unsigned long long wc[32], ww[32];
    load_wreg(C1, mbase, c0, lane, wc);
    load_wreg(W1, mbase, c0, lane, ww);
    __syncthreads();

    for (int t = 0; t < T_STEPS; ++t) {
        // ---- register prefetch of per-step DRAM operands (hidden by GEMM) --
        float pb0 = 0.f, pb1 = 0.f, psc = 1.f;
        if (lane < 16) {
            size_t row = (size_t)t*BATCH + bql;
            pb0 = __ldcg(&g_be0[row*HID + mql]);
            pb1 = __ldcg(&g_be1[row*HID + mql]);
            psc = __ldcg(&g_scale1[row]);
        }

        // ---- broadcast-load full h_{t-1} ----
        {
            const float4* s4 = (const float4*)((t == 0) ? g_hzero
                                  : (g_hall + (size_t)(t-1)*BATCH*HID));
            float4* d4 = (float4*)hb;
            #pragma unroll
            for (int i = 0; i < 8; ++i) d4[tid + 256*i] = __ldcg(s4 + tid + 256*i);
        }
        __syncthreads();

        // ---- phase A: P = h @ C1^T -> error + norm partials ----------------
        float acc[16];
        tile_mm_reg(wc, hb, r0, lane, acc);
        if (lane < 16) {
            float v = pick16(acc, lane);
            float e = pb0 - tanhf(v)*psc;
            g_err[bql*HID + mql] = e;
            float s2 = e*e;
            s2 += __shfl_xor_sync(0x0000ffffu, s2, 1);
            s2 += __shfl_xor_sync(0x0000ffffu, s2, 2);
            if (cc == 0) g_normp[bql*128 + g*2 + (c0 >> 2)] = s2;
        }
        gbar(&g_ctr[2*t]);

        // ---- load full error + reduce norm partials ------------------------
        {
            const float4* s4 = (const float4*)g_err;
            float4* d4 = (float4*)eb;
            #pragma unroll
            for (int i = 0; i < 8; ++i) d4[tid + 256*i] = __ldcg(s4 + tid + 256*i);
        }
        {
            int b = tid >> 4, j = tid & 15;
            const float4* np = (const float4*)(g_normp + b*128);
            float4 x = __ldcg(np + j);
            float4 y = __ldcg(np + 16 + j);
            float s = x.x+x.y+x.z+x.w + y.x+y.y+y.z+y.w;
            s += __shfl_xor_sync(0xffffffffu, s, 1, 16);
            s += __shfl_xor_sync(0xffffffffu, s, 2, 16);
            s += __shfl_xor_sync(0xffffffffu, s, 4, 16);
            s += __shfl_xor_sync(0xffffffffu, s, 8, 16);
            if (j == 0) snorm[b] = s;
        }
        __syncthreads();

        // ---- phase B: E = error @ W1^T -> h update -------------------------
        float acc2[16];
        tile_mm_reg(ww, eb, r0, lane, acc2);
        if (lane < 16) {
            float v   = pick16(acc2, lane);
            float rel = fminf(sqrtf(snorm[bql])/psc, 4.f);
            float sur = 1.f/(1.f + expf(-(rel - tau)/gam));
            float hv  = hb[bql*HID + mql];
            float ih  = 0.2f*hv + 0.6f*pb1 + 0.2f*sur*v;
            float gg  = sur * sga[c0 + cc];
            g_hall[((size_t)t*BATCH + bql)*HID + mql] = hv*(1.f - gg) + tanhf(ih)*gg;
        }
        gbar(&g_ctr[2*t + 1]);
    }
}

// ---------------- launch ----------------------------------------------------
extern "C" void kernel_launch(void* const* d_in, const int* in_sizes, int n_in,
                              void* d_out, int out_size)
{
    const float* feats  = (const float*)d_in[0];
    const float* B0     = (const float*)d_in[2];
    const float* C1     = (const float*)d_in[7];
    const float* B1     = (const float*)d_in[8];
    const float* W1     = (const float*)d_in[9];
    const float* a1     = (const float*)d_in[10];
    const float* tau1   = (const float*)d_in[11];
    const float* gam1   = (const float*)d_in[12];
    const float* head_w = (const float*)d_in[13];
    const float* head_b = (const float*)d_in[14];
    float* out = (float*)d_out;

    float *p_xn0, *p_be0, *p_xn1, *p_be1, *p_hall;
    cudaGetSymbolAddress((void**)&p_xn0,  g_xn0);
    cudaGetSymbolAddress((void**)&p_be0,  g_be0);
    cudaGetSymbolAddress((void**)&p_xn1,  g_xn1);
    cudaGetSymbolAddress((void**)&p_be1,  g_be1);
    cudaGetSymbolAddress((void**)&p_hall, g_hall);

    const int SCAN_SMEM = (2*BATCH*HID + COLS_PER_CTA + 16)*4;
    cudaFuncSetAttribute(scan_kernel, cudaFuncAttributeMaxDynamicSharedMemorySize, SCAN_SMEM);

    zero_scratch<<<64, 256>>>();
    xnorm0_kernel<<<(NROWS*32)/256, 256>>>(feats);

    dim3 g1(HID/64, NROWS/64);
    sgemm_nt<<<g1, 256>>>(p_xn0, MEL, B0, MEL, p_be0, HID, MEL, 0, nullptr, 0);
    xnorm1_kernel<<<(NROWS*32)/256, 256>>>();
    sgemm_nt<<<g1, 256>>>(p_xn1, HID, B1, HID, p_be1, HID, HID, 0, nullptr, 0);

    scan_kernel<<<SCAN_CTAS, 256, SCAN_SMEM>>>(C1, W1, a1, tau1, gam1);

    dim3 gh(NCLS/64, NROWS/64);
    sgemm_nt<<<gh, 256>>>(p_hall, HID, head_w,       2*HID, out, NCLS, HID, 0, nullptr, 1);
    sgemm_nt<<<gh, 256>>>(p_be1,  HID, head_w + HID, 2*HID, out, NCLS, HID, 1, head_b, 1);
}

// round 7
// speedup vs baseline: 1.3261x; 1.3261x over previous
#include <cuda_runtime.h>
#include <math.h>

#define T_STEPS 1000
#define BATCH   16
#define MEL     80
#define HID     512
#define NCLS    64
#define NROWS   (T_STEPS*BATCH)      // 16000

#define SCAN_CTAS   64
#define COLS_PER_CTA (HID/SCAN_CTAS) // 8

// ---------------- scratch (device globals; no allocation allowed) ----------
__device__ float    g_be0[NROWS*HID];
__device__ float    g_xn1[NROWS*HID];
__device__ float    g_be1[NROWS*HID];
__device__ float    g_hall[NROWS*HID];
__device__ float    g_scale1[NROWS];
__device__ float    g_err[BATCH*HID];
__device__ float    g_normp[BATCH*128];   // [b][cta*2 + half] partial norms
__device__ float    g_hzero[BATCH*HID];
__device__ unsigned g_ctr[2*T_STEPS];

__device__ __forceinline__ float clip1(float v) {
    return fminf(fmaxf(v, -1.f), 1.f);
}

// ---------------- fused: zero scratch + xnorm0 + be0 GEMM ------------------
// Warp-per-row: each warp handles 8 rows. Row r = t*16+b reads feats[b][t][:].
// Per row: norm+clip feats (80) -> smem, then be0[r, :] = xn0 @ B0^T.
__global__ __launch_bounds__(256) void fused_be0_kernel(
    const float* __restrict__ feats, const float* __restrict__ B0)
{
    __shared__ float xs[64][80];   // normalized rows, 20KB

    const int tid  = threadIdx.x;
    const int warp = tid >> 5, lane = tid & 31;
    const int r_base = blockIdx.x*64 + warp*8;

    // block 0 zeroes the scan-kernel scratch (counters + h0)
    if (blockIdx.x == 0) {
        for (int i = tid; i < 2*T_STEPS; i += 256) g_ctr[i] = 0u;
        for (int i = tid; i < BATCH*HID; i += 256) g_hzero[i] = 0.f;
    }

    // stage 1: per-row norm + clip into smem
    #pragma unroll
    for (int rr = 0; rr < 8; rr++) {
        int r = r_base + rr;
        int t = r >> 4, b = r & 15;
        const float* row = feats + ((size_t)b*T_STEPS + t)*MEL;
        float v0 = row[lane];
        float v1 = row[lane+32];
        float v2 = (lane < 16) ? row[lane+64] : 0.f;
        float s = v0*v0 + v1*v1 + v2*v2;
        #pragma unroll
        for (int off = 16; off; off >>= 1) s += __shfl_xor_sync(0xffffffffu, s, off);
        float inv = 1.f/fmaxf(sqrtf(s), 1e-6f);
        int lr = warp*8 + rr;
        xs[lr][lane]    = clip1(v0*inv);
        xs[lr][lane+32] = clip1(v1*inv);
        if (lane < 16) xs[lr][lane+64] = clip1(v2*inv);
    }
    __syncwarp();

    // stage 2: be0 rows; lane covers 4 cols per pass, 4 passes = 128 cols/lane-pass * 4
    #pragma unroll 1
    for (int q = 0; q < 4; q++) {
        int c0 = q*128 + lane*4;
        float acc[8][4];
        #pragma unroll
        for (int rr = 0; rr < 8; rr++)
            #pragma unroll
            for (int j = 0; j < 4; j++) acc[rr][j] = 0.f;

        for (int kc = 0; kc < 20; kc++) {
            float4 b40 = *(const float4*)(B0 + (size_t)(c0+0)*MEL + kc*4);
            float4 b41 = *(const float4*)(B0 + (size_t)(c0+1)*MEL + kc*4);
            float4 b42 = *(const float4*)(B0 + (size_t)(c0+2)*MEL + kc*4);
            float4 b43 = *(const float4*)(B0 + (size_t)(c0+3)*MEL + kc*4);
            #pragma unroll
            for (int rr = 0; rr < 8; rr++) {
                float4 x4 = *(const float4*)&xs[warp*8+rr][kc*4];
                acc[rr][0] += x4.x*b40.x + x4.y*b40.y + x4.z*b40.z + x4.w*b40.w;
                acc[rr][1] += x4.x*b41.x + x4.y*b41.y + x4.z*b41.z + x4.w*b41.w;
                acc[rr][2] += x4.x*b42.x + x4.y*b42.y + x4.z*b42.z + x4.w*b42.w;
                acc[rr][3] += x4.x*b43.x + x4.y*b43.y + x4.z*b43.z + x4.w*b43.w;
            }
        }
        #pragma unroll
        for (int rr = 0; rr < 8; rr++) {
            int r = r_base + rr;
            *(float4*)&g_be0[(size_t)r*HID + c0] =
                make_float4(acc[rr][0], acc[rr][1], acc[rr][2], acc[rr][3]);
        }
    }
}

// ---------------- x_norm + scale for cell1 input (be0) ---------------------
__global__ void xnorm1_kernel() {
    int w    = (blockIdx.x*blockDim.x + threadIdx.x) >> 5;
    int lane = threadIdx.x & 31;
    if (w >= NROWS) return;
    const float4* row = (const float4*)(g_be0 + (size_t)w*HID);
    float4 v[4];
    float s = 0.f;
    #pragma unroll
    for (int i = 0; i < 4; i++) {
        v[i] = row[lane + 32*i];
        s += v[i].x*v[i].x + v[i].y*v[i].y + v[i].z*v[i].z + v[i].w*v[i].w;
    }
    #pragma unroll
    for (int off = 16; off; off >>= 1) s += __shfl_xor_sync(0xffffffffu, s, off);
    float sc = fmaxf(sqrtf(s), 1e-6f);
    if (lane == 0) g_scale1[w] = sc;
    float inv = 1.f/sc;
    float4* o = (float4*)(g_xn1 + (size_t)w*HID);
    #pragma unroll
    for (int i = 0; i < 4; i++) {
        float4 u = v[i];
        u.x = clip1(u.x*inv);
        u.y = clip1(u.y*inv);
        u.z = clip1(u.z*inv);
        u.w = clip1(u.w*inv);
        o[lane + 32*i] = u;
    }
}

// ---------------- generic tiled SGEMM: C = A(M,K) @ W(N,K)^T ---------------
__global__ __launch_bounds__(256) void sgemm_nt(
    const float* __restrict__ A, int lda,
    const float* __restrict__ W, int ldw,
    float*       __restrict__ C, int ldc,
    int K, int accumulate, const float* __restrict__ bias, int remap)
{
    __shared__ float As[16][64];
    __shared__ float Ws[16][64];
    int bm = blockIdx.y*64, bn = blockIdx.x*64;
    int tid = threadIdx.x;
    int lr  = tid >> 2;
    int kq  = (tid & 3)*4;
    int tx  = tid & 15, ty = tid >> 4;
    float acc[4][4];
    #pragma unroll
    for (int i=0;i<4;i++)
        #pragma unroll
        for (int j=0;j<4;j++) acc[i][j]=0.f;

    for (int k0 = 0; k0 < K; k0 += 16) {
        float4 av = *(const float4*)(A + (size_t)(bm+lr)*lda + k0 + kq);
        float4 wv = *(const float4*)(W + (size_t)(bn+lr)*ldw + k0 + kq);
        As[kq+0][lr]=av.x; As[kq+1][lr]=av.y; As[kq+2][lr]=av.z; As[kq+3][lr]=av.w;
        Ws[kq+0][lr]=wv.x; Ws[kq+1][lr]=wv.y; Ws[kq+2][lr]=wv.z; Ws[kq+3][lr]=wv.w;
        __syncthreads();
        #pragma unroll
        for (int k = 0; k < 16; k++) {
            float4 a4 = *(float4*)&As[k][ty*4];
            float4 w4 = *(float4*)&Ws[k][tx*4];
            float ar[4] = {a4.x, a4.y, a4.z, a4.w};
            float wr[4] = {w4.x, w4.y, w4.z, w4.w};
            #pragma unroll
            for (int i=0;i<4;i++)
                #pragma unroll
                for (int j=0;j<4;j++) acc[i][j] += ar[i]*wr[j];
        }
        __syncthreads();
    }
    #pragma unroll
    for (int i = 0; i < 4; i++) {
        int r = bm + ty*4 + i;
        int orow = remap ? ((r & 15)*T_STEPS + (r >> 4)) : r;
        #pragma unroll
        for (int j = 0; j < 4; j++) {
            int cidx = bn + tx*4 + j;
            float val = acc[i][j];
            if (bias) val += bias[cidx];
            float* p = C + (size_t)orow*ldc + cidx;
            if (accumulate) val += *p;
            *p = val;
        }
    }
}

// ---------------- fence-free grid barrier (release/acquire) -----------------
__device__ __forceinline__ void gbar(unsigned* c) {
    __syncthreads();
    if (threadIdx.x == 0) {
        asm volatile("red.release.gpu.global.add.u32 [%0], 1;" :: "l"(c) : "memory");
        unsigned v;
        do {
            asm volatile("ld.acquire.gpu.global.u32 %0, [%1];" : "=r"(v) : "l"(c) : "memory");
        } while (v < SCAN_CTAS);
    }
    __syncthreads();
}

// ---------------- inner GEMM: 4 rows x 4 cols per warp, K split on lanes ----
__device__ __forceinline__ void tile_mm(const float* __restrict__ wgt,
                                        const float* __restrict__ src,
                                        int r0, int c0, int lane, float acc[16])
{
    #pragma unroll
    for (int j = 0; j < 16; j++) acc[j] = 0.f;
    #pragma unroll
    for (int i = 0; i < 4; i++) {
        int kf = (lane + 32*i)*4;
        float4 w0 = *(const float4*)&wgt[(c0+0)*HID + kf];
        float4 w1 = *(const float4*)&wgt[(c0+1)*HID + kf];
        float4 w2 = *(const float4*)&wgt[(c0+2)*HID + kf];
        float4 w3 = *(const float4*)&wgt[(c0+3)*HID + kf];
        #pragma unroll
        for (int r = 0; r < 4; r++) {
            float4 h = *(const float4*)&src[(r0+r)*HID + kf];
            acc[r*4+0] += h.x*w0.x + h.y*w0.y + h.z*w0.z + h.w*w0.w;
            acc[r*4+1] += h.x*w1.x + h.y*w1.y + h.z*w1.z + h.w*w1.w;
            acc[r*4+2] += h.x*w2.x + h.y*w2.y + h.z*w2.z + h.w*w2.w;
            acc[r*4+3] += h.x*w3.x + h.y*w3.y + h.z*w3.z + h.w*w3.w;
        }
    }
    #pragma unroll
    for (int off = 16; off; off >>= 1) {
        #pragma unroll
        for (int j = 0; j < 16; j++)
            acc[j] += __shfl_xor_sync(0xffffffffu, acc[j], off);
    }
}

__device__ __forceinline__ float pick16(const float acc[16], int lane) {
    float v = acc[0];
    #pragma unroll
    for (int j = 1; j < 16; j++) if (lane == j) v = acc[j];
    return v;
}

// ---------------- persistent sequential scan over T ------------------------
__global__ __launch_bounds__(256, 1) void scan_kernel(
    const float* __restrict__ C1, const float* __restrict__ W1,
    const float* __restrict__ a1, const float* __restrict__ taup,
    const float* __restrict__ gamp)
{
    extern __shared__ float sm[];
    float* wC   = sm;                          // 8*512
    float* wW   = wC + COLS_PER_CTA*HID;       // 8*512
    float* hb   = wW + COLS_PER_CTA*HID;       // 16*512 (h_{t-1})
    float* eb   = hb + BATCH*HID;              // 16*512 (error)
    float* sga  = eb + BATCH*HID;              // 8
    float* snorm= sga + COLS_PER_CTA;          // 16

    const int g = blockIdx.x, tid = threadIdx.x;
    const int mbase = g*COLS_PER_CTA;

    for (int i = tid; i < COLS_PER_CTA*HID; i += 256) {
        int mm = i >> 9, k = i & (HID-1);
        wC[i] = C1[(size_t)(mbase+mm)*HID + k];
        wW[i] = W1[(size_t)(mbase+mm)*HID + k];
    }
    if (tid < COLS_PER_CTA) sga[tid] = 1.f/(1.f + expf(-a1[mbase+tid]));
    const float tau = taup[0], gam = gamp[0];
    __syncthreads();

    const int warp = tid >> 5, lane = tid & 31;
    const int r0 = (warp & 3)*4;      // batch-row group
    const int c0 = (warp >> 2)*4;     // col group within CTA slice
    const int rr = lane >> 2, cc = lane & 3;
    const int bql = r0 + rr;                  // this lane's batch row (lane<16)
    const int mql = mbase + c0 + cc;          // this lane's output column

    for (int t = 0; t < T_STEPS; ++t) {
        // ---- register prefetch of per-step DRAM operands (hidden by GEMM) --
        float pb0 = 0.f, pb1 = 0.f, psc = 1.f;
        if (lane < 16) {
            size_t row = (size_t)t*BATCH + bql;
            pb0 = __ldcg(&g_be0[row*HID + mql]);
            pb1 = __ldcg(&g_be1[row*HID + mql]);
            psc = __ldcg(&g_scale1[row]);
        }

        // ---- broadcast-load full h_{t-1} ----
        {
            const float4* s4 = (const float4*)((t == 0) ? g_hzero
                                  : (g_hall + (size_t)(t-1)*BATCH*HID));
            float4* d4 = (float4*)hb;
            #pragma unroll
            for (int i = 0; i < 8; ++i) d4[tid + 256*i] = __ldcg(s4 + tid + 256*i);
        }
        __syncthreads();

        // ---- phase A: P = h @ C1^T -> error + norm partials ----------------
        float acc[16];
        tile_mm(wC, hb, r0, c0, lane, acc);
        if (lane < 16) {
            float v = pick16(acc, lane);
            float e = pb0 - tanhf(v)*psc;
            g_err[bql*HID + mql] = e;
            float s2 = e*e;
            s2 += __shfl_xor_sync(0x0000ffffu, s2, 1);
            s2 += __shfl_xor_sync(0x0000ffffu, s2, 2);
            if (cc == 0) g_normp[bql*128 + g*2 + (c0 >> 2)] = s2;
        }
        gbar(&g_ctr[2*t]);

        // ---- load full error + reduce norm partials ------------------------
        {
            const float4* s4 = (const float4*)g_err;
            float4* d4 = (float4*)eb;
            #pragma unroll
            for (int i = 0; i < 8; ++i) d4[tid + 256*i] = __ldcg(s4 + tid + 256*i);
        }
        {
            int b = tid >> 4, j = tid & 15;
            const float4* np = (const float4*)(g_normp + b*128);
            float4 x = __ldcg(np + j);
            float4 y = __ldcg(np + 16 + j);
            float s = x.x+x.y+x.z+x.w + y.x+y.y+y.z+y.w;
            s += __shfl_xor_sync(0xffffffffu, s, 1, 16);
            s += __shfl_xor_sync(0xffffffffu, s, 2, 16);
            s += __shfl_xor_sync(0xffffffffu, s, 4, 16);
            s += __shfl_xor_sync(0xffffffffu, s, 8, 16);
            if (j == 0) snorm[b] = s;
        }
        __syncthreads();

        // ---- phase B: E = error @ W1^T -> h update -------------------------
        float acc2[16];
        tile_mm(wW, eb, r0, c0, lane, acc2);
        if (lane < 16) {
            float v   = pick16(acc2, lane);
            float rel = fminf(sqrtf(snorm[bql])/psc, 4.f);
            float sur = 1.f/(1.f + expf(-(rel - tau)/gam));
            float hv  = hb[bql*HID + mql];
            float ih  = 0.2f*hv + 0.6f*pb1 + 0.2f*sur*v;
            float gg  = sur * sga[c0 + cc];
            g_hall[((size_t)t*BATCH + bql)*HID + mql] = hv*(1.f - gg) + tanhf(ih)*gg;
        }
        gbar(&g_ctr[2*t + 1]);
    }
}

// ---------------- launch ----------------------------------------------------
extern "C" void kernel_launch(void* const* d_in, const int* in_sizes, int n_in,
                              void* d_out, int out_size)
{
    const float* feats  = (const float*)d_in[0];
    const float* B0     = (const float*)d_in[2];
    const float* C1     = (const float*)d_in[7];
    const float* B1     = (const float*)d_in[8];
    const float* W1     = (const float*)d_in[9];
    const float* a1     = (const float*)d_in[10];
    const float* tau1   = (const float*)d_in[11];
    const float* gam1   = (const float*)d_in[12];
    const float* head_w = (const float*)d_in[13];
    const float* head_b = (const float*)d_in[14];
    float* out = (float*)d_out;

    float *p_xn1, *p_be1, *p_hall;
    cudaGetSymbolAddress((void**)&p_xn1,  g_xn1);
    cudaGetSymbolAddress((void**)&p_be1,  g_be1);
    cudaGetSymbolAddress((void**)&p_hall, g_hall);

    const int SCAN_SMEM = (2*COLS_PER_CTA*HID + 2*BATCH*HID + COLS_PER_CTA + 16)*4;
    cudaFuncSetAttribute(scan_kernel, cudaFuncAttributeMaxDynamicSharedMemorySize, SCAN_SMEM);

    // launch #0: fused zero + xnorm0 + be0 GEMM
    fused_be0_kernel<<<NROWS/64, 256>>>(feats, B0);
    // launch #1
    xnorm1_kernel<<<(NROWS*32)/256, 256>>>();
    // launch #2: be1 = xn1 @ B1^T
    dim3 g1(HID/64, NROWS/64);
    sgemm_nt<<<g1, 256>>>(p_xn1, HID, B1, HID, p_be1, HID, HID, 0, nullptr, 0);
    // launch #3: the scan (target of ncu -s 5 -c 1 capture)
    scan_kernel<<<SCAN_CTAS, 256, SCAN_SMEM>>>(C1, W1, a1, tau1, gam1);
    // head
    dim3 gh(NCLS/64, NROWS/64);
    sgemm_nt<<<gh, 256>>>(p_hall, HID, head_w,       2*HID, out, NCLS, HID, 0, nullptr, 1);
    sgemm_nt<<<gh, 256>>>(p_be1,  HID, head_w + HID, 2*HID, out, NCLS, HID, 1, head_b, 1);
}

// round 8
// speedup vs baseline: 1.6998x; 1.2818x over previous
#include <cuda_runtime.h>
#include <math.h>

#define T_STEPS 1000
#define BATCH   16
#define MEL     80
#define HID     512
#define NCLS    64
#define NROWS   (T_STEPS*BATCH)      // 16000

#define NGROUPS   8
#define GCTAS     16                 // CTAs per group (sync domain)
#define SCAN_CTAS (NGROUPS*GCTAS)    // 128
#define GCOLS     32                 // cols per CTA
#define WSL       20                 // padded k-slice stride (16 data + 4 pad floats)

// ---------------- scratch (device globals; no allocation allowed) ----------
__device__ float    g_be0[NROWS*HID];
__device__ float    g_xn1[NROWS*HID];
__device__ float    g_be1[NROWS*HID];
__device__ float    g_hall[NROWS*HID];
__device__ float    g_scale1[NROWS];
__device__ float    g_err[BATCH*HID];
__device__ float    g_normp[BATCH*128];   // [b][cta_in_group*8 + warp]
__device__ float    g_hzero[BATCH*HID];
__device__ unsigned g_ctr2[NGROUPS*2048]; // per-group per-step counters

__device__ __forceinline__ float clip1(float v) {
    return fminf(fmaxf(v, -1.f), 1.f);
}

// ---------------- fused: zero scratch + xnorm0 + be0 GEMM ------------------
__global__ __launch_bounds__(256) void fused_be0_kernel(
    const float* __restrict__ feats, const float* __restrict__ B0)
{
    __shared__ float xs[64][80];

    const int tid  = threadIdx.x;
    const int warp = tid >> 5, lane = tid & 31;
    const int r_base = blockIdx.x*64 + warp*8;

    if (blockIdx.x == 0) {
        for (int i = tid; i < NGROUPS*2048; i += 256) g_ctr2[i] = 0u;
        for (int i = tid; i < BATCH*HID; i += 256) g_hzero[i] = 0.f;
    }

    #pragma unroll
    for (int rr = 0; rr < 8; rr++) {
        int r = r_base + rr;
        int t = r >> 4, b = r & 15;
        const float* row = feats + ((size_t)b*T_STEPS + t)*MEL;
        float v0 = row[lane];
        float v1 = row[lane+32];
        float v2 = (lane < 16) ? row[lane+64] : 0.f;
        float s = v0*v0 + v1*v1 + v2*v2;
        #pragma unroll
        for (int off = 16; off; off >>= 1) s += __shfl_xor_sync(0xffffffffu, s, off);
        float inv = 1.f/fmaxf(sqrtf(s), 1e-6f);
        int lr = warp*8 + rr;
        xs[lr][lane]    = clip1(v0*inv);
        xs[lr][lane+32] = clip1(v1*inv);
        if (lane < 16) xs[lr][lane+64] = clip1(v2*inv);
    }
    __syncwarp();

    #pragma unroll 1
    for (int q = 0; q < 4; q++) {
        int c0 = q*128 + lane*4;
        float acc[8][4];
        #pragma unroll
        for (int rr = 0; rr < 8; rr++)
            #pragma unroll
            for (int j = 0; j < 4; j++) acc[rr][j] = 0.f;

        for (int kc = 0; kc < 20; kc++) {
            float4 b40 = *(const float4*)(B0 + (size_t)(c0+0)*MEL + kc*4);
            float4 b41 = *(const float4*)(B0 + (size_t)(c0+1)*MEL + kc*4);
            float4 b42 = *(const float4*)(B0 + (size_t)(c0+2)*MEL + kc*4);
            float4 b43 = *(const float4*)(B0 + (size_t)(c0+3)*MEL + kc*4);
            #pragma unroll
            for (int rr = 0; rr < 8; rr++) {
                float4 x4 = *(const float4*)&xs[warp*8+rr][kc*4];
                acc[rr][0] += x4.x*b40.x + x4.y*b40.y + x4.z*b40.z + x4.w*b40.w;
                acc[rr][1] += x4.x*b41.x + x4.y*b41.y + x4.z*b41.z + x4.w*b41.w;
                acc[rr][2] += x4.x*b42.x + x4.y*b42.y + x4.z*b42.z + x4.w*b42.w;
                acc[rr][3] += x4.x*b43.x + x4.y*b43.y + x4.z*b43.z + x4.w*b43.w;
            }
        }
        #pragma unroll
        for (int rr = 0; rr < 8; rr++) {
            int r = r_base + rr;
            *(float4*)&g_be0[(size_t)r*HID + c0] =
                make_float4(acc[rr][0], acc[rr][1], acc[rr][2], acc[rr][3]);
        }
    }
}

// ---------------- x_norm + scale for cell1 input (be0) ---------------------
__global__ void xnorm1_kernel() {
    int w    = (blockIdx.x*blockDim.x + threadIdx.x) >> 5;
    int lane = threadIdx.x & 31;
    if (w >= NROWS) return;
    const float4* row = (const float4*)(g_be0 + (size_t)w*HID);
    float4 v[4];
    float s = 0.f;
    #pragma unroll
    for (int i = 0; i < 4; i++) {
        v[i] = row[lane + 32*i];
        s += v[i].x*v[i].x + v[i].y*v[i].y + v[i].z*v[i].z + v[i].w*v[i].w;
    }
    #pragma unroll
    for (int off = 16; off; off >>= 1) s += __shfl_xor_sync(0xffffffffu, s, off);
    float sc = fmaxf(sqrtf(s), 1e-6f);
    if (lane == 0) g_scale1[w] = sc;
    float inv = 1.f/sc;
    float4* o = (float4*)(g_xn1 + (size_t)w*HID);
    #pragma unroll
    for (int i = 0; i < 4; i++) {
        float4 u = v[i];
        u.x = clip1(u.x*inv);
        u.y = clip1(u.y*inv);
        u.z = clip1(u.z*inv);
        u.w = clip1(u.w*inv);
        o[lane + 32*i] = u;
    }
}

// ---------------- generic tiled SGEMM: C = A(M,K) @ W(N,K)^T ---------------
__global__ __launch_bounds__(256) void sgemm_nt(
    const float* __restrict__ A, int lda,
    const float* __restrict__ W, int ldw,
    float*       __restrict__ C, int ldc,
    int K, int accumulate, const float* __restrict__ bias, int remap)
{
    __shared__ float As[16][64];
    __shared__ float Ws[16][64];
    int bm = blockIdx.y*64, bn = blockIdx.x*64;
    int tid = threadIdx.x;
    int lr  = tid >> 2;
    int kq  = (tid & 3)*4;
    int tx  = tid & 15, ty = tid >> 4;
    float acc[4][4];
    #pragma unroll
    for (int i=0;i<4;i++)
        #pragma unroll
        for (int j=0;j<4;j++) acc[i][j]=0.f;

    for (int k0 = 0; k0 < K; k0 += 16) {
        float4 av = *(const float4*)(A + (size_t)(bm+lr)*lda + k0 + kq);
        float4 wv = *(const float4*)(W + (size_t)(bn+lr)*ldw + k0 + kq);
        As[kq+0][lr]=av.x; As[kq+1][lr]=av.y; As[kq+2][lr]=av.z; As[kq+3][lr]=av.w;
        Ws[kq+0][lr]=wv.x; Ws[kq+1][lr]=wv.y; Ws[kq+2][lr]=wv.z; Ws[kq+3][lr]=wv.w;
        __syncthreads();
        #pragma unroll
        for (int k = 0; k < 16; k++) {
            float4 a4 = *(float4*)&As[k][ty*4];
            float4 w4 = *(float4*)&Ws[k][tx*4];
            float ar[4] = {a4.x, a4.y, a4.z, a4.w};
            float wr[4] = {w4.x, w4.y, w4.z, w4.w};
            #pragma unroll
            for (int i=0;i<4;i++)
                #pragma unroll
                for (int j=0;j<4;j++) acc[i][j] += ar[i]*wr[j];
        }
        __syncthreads();
    }
    #pragma unroll
    for (int i = 0; i < 4; i++) {
        int r = bm + ty*4 + i;
        int orow = remap ? ((r & 15)*T_STEPS + (r >> 4)) : r;
        #pragma unroll
        for (int j = 0; j < 4; j++) {
            int cidx = bn + tx*4 + j;
            float val = acc[i][j];
            if (bias) val += bias[cidx];
            float* p = C + (size_t)orow*ldc + cidx;
            if (accumulate) val += *p;
            *p = val;
        }
    }
}

// ---------------- group barrier: 16 arrivals, release/acquire ---------------
__device__ __forceinline__ void gbar(unsigned* c) {
    __syncthreads();
    if (threadIdx.x == 0) {
        asm volatile("red.release.gpu.global.add.u32 [%0], 1;" :: "l"(c) : "memory");
        unsigned v;
        do {
            asm volatile("ld.acquire.gpu.global.u32 %0, [%1];" : "=r"(v) : "l"(c) : "memory");
        } while (v < GCTAS);
    }
    __syncthreads();
}

// ---------------- persistent scan: 8 groups x 16 CTAs, 2 batch rows/group ---
__global__ __launch_bounds__(256, 1) void scan_kernel(
    const float* __restrict__ C1, const float* __restrict__ W1,
    const float* __restrict__ a1, const float* __restrict__ taup,
    const float* __restrict__ gamp)
{
    extern __shared__ float sm[];
    float* wC   = sm;                       // 32*32*20 = 20480
    float* wW   = wC + GCOLS*32*WSL;        // 20480
    float* hb   = wW + GCOLS*32*WSL;        // 64*20 = 1280 (2 rows, padded slices)
    float* eb   = hb + 64*WSL;              // 1280
    float* sga  = eb + 64*WSL;              // 32
    float* snorm= sga + GCOLS;              // 2

    const int cta = blockIdx.x;
    const int g   = cta >> 4;               // group = batch pair
    const int cg  = cta & 15;               // CTA in group
    const int tid = threadIdx.x;
    const int mbase = cg*GCOLS;             // col base in [0,512)
    const int b0 = g*2;

    // weights into padded conflict-free slice layout: slice (m*32 + k/16), len 16
    for (int idx = tid; idx < GCOLS*HID; idx += 256) {
        int m = idx >> 9, k = idx & 511;
        int sl = (m*32 + (k>>4))*WSL + (k&15);
        wC[sl] = C1[(size_t)(mbase+m)*HID + k];
        wW[sl] = W1[(size_t)(mbase+m)*HID + k];
    }
    if (tid < GCOLS) sga[tid] = 1.f/(1.f + expf(-a1[mbase+tid]));
    const float tau = taup[0], gam = gamp[0];
    unsigned* ctr = g_ctr2 + g*2048;
    __syncthreads();

    const int warp = tid >> 5, lane = tid & 31;   // warp covers 4 cols, lane = k-slice
    const float* wc0 = &wC[((warp*4+0)*32 + lane)*WSL];
    const float* wc1 = &wC[((warp*4+1)*32 + lane)*WSL];
    const float* wc2 = &wC[((warp*4+2)*32 + lane)*WSL];
    const float* wc3 = &wC[((warp*4+3)*32 + lane)*WSL];
    const float* ww0 = &wW[((warp*4+0)*32 + lane)*WSL];
    const float* ww1 = &wW[((warp*4+1)*32 + lane)*WSL];
    const float* ww2 = &wW[((warp*4+2)*32 + lane)*WSL];
    const float* ww3 = &wW[((warp*4+3)*32 + lane)*WSL];
    const float* hs0 = &hb[(lane)*WSL];
    const float* hs1 = &hb[(32+lane)*WSL];
    const float* es0 = &eb[(lane)*WSL];
    const float* es1 = &eb[(32+lane)*WSL];

    const int cloc = warp*4 + (lane & 3);   // this lane's col (owners: lane<4)
    const int col  = mbase + cloc;
    const int hv0i = ((col >> 4))*WSL + (col & 15);       // row0 slice of h
    const int hv1i = ((32 + (col >> 4)))*WSL + (col & 15);

    for (int t = 0; t < T_STEPS; ++t) {
        // per-step operand prefetch (owners only)
        float pb00=0.f, pb01=0.f, pb10=0.f, pb11=0.f;
        if (lane < 4) {
            size_t r = ((size_t)t*BATCH + b0)*HID + col;
            pb00 = __ldcg(&g_be0[r]);
            pb01 = __ldcg(&g_be0[r + HID]);
            pb10 = __ldcg(&g_be1[r]);
            pb11 = __ldcg(&g_be1[r + HID]);
        }
        float psc0 = __ldcg(&g_scale1[t*BATCH + b0]);
        float psc1 = __ldcg(&g_scale1[t*BATCH + b0 + 1]);

        // load h (2 rows, 4KB) into padded smem
        {
            const float* src = (t == 0) ? (g_hzero + b0*HID)
                                        : (g_hall + ((size_t)(t-1)*BATCH + b0)*HID);
            float4 v = __ldcg(((const float4*)src) + tid);
            int row = tid >> 7, k4 = (tid & 127)*4;
            *(float4*)&hb[(row*32 + (k4>>4))*WSL + (k4&15)] = v;
        }
        __syncthreads();

        // ---- phase A: P = h @ C1^T (4 cols x 2 rows per warp, 32-way k-split)
        float a00=0,a01=0,a10=0,a11=0,a20=0,a21=0,a30=0,a31=0;
        #pragma unroll
        for (int i = 0; i < 4; i++) {
            float4 x0 = *(const float4*)&hs0[i*4];
            float4 x1 = *(const float4*)&hs1[i*4];
            float4 u0 = *(const float4*)&wc0[i*4];
            float4 u1 = *(const float4*)&wc1[i*4];
            float4 u2 = *(const float4*)&wc2[i*4];
            float4 u3 = *(const float4*)&wc3[i*4];
            a00 += u0.x*x0.x + u0.y*x0.y + u0.z*x0.z + u0.w*x0.w;
            a01 += u0.x*x1.x + u0.y*x1.y + u0.z*x1.z + u0.w*x1.w;
            a10 += u1.x*x0.x + u1.y*x0.y + u1.z*x0.z + u1.w*x0.w;
            a11 += u1.x*x1.x + u1.y*x1.y + u1.z*x1.z + u1.w*x1.w;
            a20 += u2.x*x0.x + u2.y*x0.y + u2.z*x0.z + u2.w*x0.w;
            a21 += u2.x*x1.x + u2.y*x1.y + u2.z*x1.z + u2.w*x1.w;
            a30 += u3.x*x0.x + u3.y*x0.y + u3.z*x0.z + u3.w*x0.w;
            a31 += u3.x*x1.x + u3.y*x1.y + u3.z*x1.z + u3.w*x1.w;
        }
        #pragma unroll
        for (int off = 16; off; off >>= 1) {
            a00 += __shfl_xor_sync(0xffffffffu, a00, off);
            a01 += __shfl_xor_sync(0xffffffffu, a01, off);
            a10 += __shfl_xor_sync(0xffffffffu, a10, off);
            a11 += __shfl_xor_sync(0xffffffffu, a11, off);
            a20 += __shfl_xor_sync(0xffffffffu, a20, off);
            a21 += __shfl_xor_sync(0xffffffffu, a21, off);
            a30 += __shfl_xor_sync(0xffffffffu, a30, off);
            a31 += __shfl_xor_sync(0xffffffffu, a31, off);
        }
        float e0 = 0.f, e1 = 0.f;
        if (lane < 4) {
            float p0 = a00, p1 = a01;
            if (lane == 1) { p0 = a10; p1 = a11; }
            if (lane == 2) { p0 = a20; p1 = a21; }
            if (lane == 3) { p0 = a30; p1 = a31; }
            e0 = pb00 - tanhf(p0)*psc0;
            e1 = pb01 - tanhf(p1)*psc1;
            g_err[b0*HID + col]     = e0;
            g_err[(b0+1)*HID + col] = e1;
        }
        float s0 = e0*e0, s1 = e1*e1;     // non-owners contribute 0
        #pragma unroll
        for (int off = 16; off; off >>= 1) {
            s0 += __shfl_xor_sync(0xffffffffu, s0, off);
            s1 += __shfl_xor_sync(0xffffffffu, s1, off);
        }
        if (lane == 0) {
            g_normp[b0*128     + cg*8 + warp] = s0;
            g_normp[(b0+1)*128 + cg*8 + warp] = s1;
        }
        gbar(ctr + 2*t);

        // load full error (2 rows) + reduce norm partials
        {
            float4 v = __ldcg(((const float4*)(g_err + b0*HID)) + tid);
            int row = tid >> 7, k4 = (tid & 127)*4;
            *(float4*)&eb[(row*32 + (k4>>4))*WSL + (k4&15)] = v;
        }
        if (warp < 2) {
            float4 v = __ldcg(((const float4*)(g_normp + (b0+warp)*128)) + lane);
            float s = v.x + v.y + v.z + v.w;
            #pragma unroll
            for (int off = 16; off; off >>= 1) s += __shfl_xor_sync(0xffffffffu, s, off);
            if (lane == 0) snorm[warp] = s;
        }
        __syncthreads();

        // ---- phase B: E = err @ W1^T -> h update ----
        float b00=0,b01=0,b10=0,b11=0,b20=0,b21=0,b30=0,b31=0;
        #pragma unroll
        for (int i = 0; i < 4; i++) {
            float4 x0 = *(const float4*)&es0[i*4];
            float4 x1 = *(const float4*)&es1[i*4];
            float4 u0 = *(const float4*)&ww0[i*4];
            float4 u1 = *(const float4*)&ww1[i*4];
            float4 u2 = *(const float4*)&ww2[i*4];
            float4 u3 = *(const float4*)&ww3[i*4];
            b00 += u0.x*x0.x + u0.y*x0.y + u0.z*x0.z + u0.w*x0.w;
            b01 += u0.x*x1.x + u0.y*x1.y + u0.z*x1.z + u0.w*x1.w;
            b10 += u1.x*x0.x + u1.y*x0.y + u1.z*x0.z + u1.w*x0.w;
            b11 += u1.x*x1.x + u1.y*x1.y + u1.z*x1.z + u1.w*x1.w;
            b20 += u2.x*x0.x + u2.y*x0.y + u2.z*x0.z + u2.w*x0.w;
            b21 += u2.x*x1.x + u2.y*x1.y + u2.z*x1.z + u2.w*x1.w;
            b30 += u3.x*x0.x + u3.y*x0.y + u3.z*x0.z + u3.w*x0.w;
            b31 += u3.x*x1.x + u3.y*x1.y + u3.z*x1.z + u3.w*x1.w;
        }
        #pragma unroll
        for (int off = 16; off; off >>= 1) {
            b00 += __shfl_xor_sync(0xffffffffu, b00, off);
            b01 += __shfl_xor_sync(0xffffffffu, b01, off);
            b10 += __shfl_xor_sync(0xffffffffu, b10, off);
            b11 += __shfl_xor_sync(0xffffffffu, b11, off);
            b20 += __shfl_xor_sync(0xffffffffu, b20, off);
            b21 += __shfl_xor_sync(0xffffffffu, b21, off);
            b30 += __shfl_xor_sync(0xffffffffu, b30, off);
            b31 += __shfl_xor_sync(0xffffffffu, b31, off);
        }
        if (lane < 4) {
            float q0 = b00, q1 = b01;
            if (lane == 1) { q0 = b10; q1 = b11; }
            if (lane == 2) { q0 = b20; q1 = b21; }
            if (lane == 3) { q0 = b30; q1 = b31; }
            float rel0 = fminf(sqrtf(snorm[0])/psc0, 4.f);
            float rel1 = fminf(sqrtf(snorm[1])/psc1, 4.f);
            float sur0 = 1.f/(1.f + expf(-(rel0 - tau)/gam));
            float sur1 = 1.f/(1.f + expf(-(rel1 - tau)/gam));
            float hv0 = hb[hv0i];
            float hv1 = hb[hv1i];
            float ih0 = 0.2f*hv0 + 0.6f*pb10 + 0.2f*sur0*q0;
            float ih1 = 0.2f*hv1 + 0.6f*pb11 + 0.2f*sur1*q1;
            float sg  = sga[cloc];
            float gg0 = sur0*sg, gg1 = sur1*sg;
            size_t orow = ((size_t)t*BATCH + b0)*HID + col;
            g_hall[orow]       = hv0*(1.f - gg0) + tanhf(ih0)*gg0;
            g_hall[orow + HID] = hv1*(1.f - gg1) + tanhf(ih1)*gg1;
        }
        gbar(ctr + 2*t + 1);
    }
}

// ---------------- launch ----------------------------------------------------
extern "C" void kernel_launch(void* const* d_in, const int* in_sizes, int n_in,
                              void* d_out, int out_size)
{
    const float* feats  = (const float*)d_in[0];
    const float* B0     = (const float*)d_in[2];
    const float* C1     = (const float*)d_in[7];
    const float* B1     = (const float*)d_in[8];
    const float* W1     = (const float*)d_in[9];
    const float* a1     = (const float*)d_in[10];
    const float* tau1   = (const float*)d_in[11];
    const float* gam1   = (const float*)d_in[12];
    const float* head_w = (const float*)d_in[13];
    const float* head_b = (const float*)d_in[14];
    float* out = (float*)d_out;

    float *p_xn1, *p_be1, *p_hall;
    cudaGetSymbolAddress((void**)&p_xn1,  g_xn1);
    cudaGetSymbolAddress((void**)&p_be1,  g_be1);
    cudaGetSymbolAddress((void**)&p_hall, g_hall);

    const int SCAN_SMEM = (2*GCOLS*32*WSL + 2*64*WSL + GCOLS + 2 + 30)*4;
    cudaFuncSetAttribute(scan_kernel, cudaFuncAttributeMaxDynamicSharedMemorySize, SCAN_SMEM);

    // launch #0: fused zero + xnorm0 + be0 GEMM
    fused_be0_kernel<<<NROWS/64, 256>>>(feats, B0);
    // launch #1
    xnorm1_kernel<<<(NROWS*32)/256, 256>>>();
    // launch #2: be1 = xn1 @ B1^T
    dim3 g1(HID/64, NROWS/64);
    sgemm_nt<<<g1, 256>>>(p_xn1, HID, B1, HID, p_be1, HID, HID, 0, nullptr, 0);
    // launch #3: the scan (ncu capture target)
    scan_kernel<<<SCAN_CTAS, 256, SCAN_SMEM>>>(C1, W1, a1, tau1, gam1);
    // head
    dim3 gh(NCLS/64, NROWS/64);
    sgemm_nt<<<gh, 256>>>(p_hall, HID, head_w,       2*HID, out, NCLS, HID, 0, nullptr, 1);
    sgemm_nt<<<gh, 256>>>(p_be1,  HID, head_w + HID, 2*HID, out, NCLS, HID, 1, head_b, 1);
}